// round 14
// baseline (speedup 1.0000x reference)
#include <cuda_runtime.h>
#include <cuda_fp16.h>
#include <cstdint>
#include <cstddef>

#define TT 8192
#define DD 2048
#define EE 8
#define NROWS 9216
#define MAX_MTILES 72    /* ceil(8192/128) + 8 slack */

#define MT 128           /* CTA tile M */
#define NT 128           /* CTA tile N */
#define KC 64            /* K per chunk (row = 128 bytes fp16) */
#define STAGES 3
#define CHUNKS (DD/KC)   /* 32 */
#define A_BYTES (MT*KC*2)             /* 16384 */
#define B_BYTES (NT*KC*2)             /* 16384 */
#define STAGE_BYTES (A_BYTES+B_BYTES) /* 32768 */
#define SMEM_NEED (STAGES*STAGE_BYTES)/* 98304 */

// ---------------- device scratch ----------------
__device__ __align__(16) __half g_xf[(size_t)TT*DD];     /* token-ordered fp16 x */
__device__ __align__(16) __half g_Wf[(size_t)EE*DD*DD];  /* fp16 W */
__device__ int   g_expert[TT];
__device__ float g_topp[TT];
__device__ int   g_row2tok[NROWS];
__device__ int   g_cnt[EE];
__device__ int   g_cursor[EE];
__device__ float g_tpsum[EE];

// ---------------- helpers ----------------
__device__ __forceinline__ uint32_t smem_u32(const void* p) {
    uint32_t a;
    asm("{ .reg .u64 t; cvta.to.shared.u64 t, %1; cvt.u32.u64 %0, t; }" : "=r"(a) : "l"(p));
    return a;
}
__device__ __forceinline__ void cp_async16(uint32_t dst, const void* src) {
    asm volatile("cp.async.cg.shared.global [%0], [%1], 16;" :: "r"(dst), "l"(src) : "memory");
}
// cp.async with runtime src-size (0 => full zero-fill of the 16B)
__device__ __forceinline__ void cp_async16z(uint32_t dst, const void* src, uint32_t srcsz) {
    asm volatile("cp.async.cg.shared.global [%0], [%1], 16, %2;"
                 :: "r"(dst), "l"(src), "r"(srcsz) : "memory");
}
__device__ __forceinline__ uint2 cvt4_h(float4 v) {
    __half2 a = __floats2half2_rn(v.x, v.y);
    __half2 b = __floats2half2_rn(v.z, v.w);
    uint2 r;
    r.x = *(uint32_t*)&a; r.y = *(uint32_t*)&b;
    return r;
}
__device__ __forceinline__ void ldsm_x4(uint32_t& r0, uint32_t& r1, uint32_t& r2, uint32_t& r3,
                                        uint32_t addr) {
    asm volatile("ldmatrix.sync.aligned.m8n8.x4.shared.b16 {%0,%1,%2,%3}, [%4];"
                 : "=r"(r0), "=r"(r1), "=r"(r2), "=r"(r3) : "r"(addr));
}
__device__ __forceinline__ void mma_f16(float* c, const uint32_t* a, const uint32_t* b) {
    asm volatile(
        "mma.sync.aligned.m16n8k16.row.col.f32.f16.f16.f32 "
        "{%0,%1,%2,%3}, {%4,%5,%6,%7}, {%8,%9}, {%0,%1,%2,%3};"
        : "+f"(c[0]), "+f"(c[1]), "+f"(c[2]), "+f"(c[3])
        : "r"(a[0]), "r"(a[1]), "r"(a[2]), "r"(a[3]), "r"(b[0]), "r"(b[1]));
}

// ---------------- small kernels ----------------
__global__ void k_reset() {
    int i = blockIdx.x * 256 + threadIdx.x;
    if (i < NROWS) g_row2tok[i] = -1;
    if (blockIdx.x == 0 && threadIdx.x < EE) {
        g_cnt[threadIdx.x] = 0; g_cursor[threadIdx.x] = 0; g_tpsum[threadIdx.x] = 0.f;
    }
}

// fused: blocks [0,1024) = router (+x fp16 conversion), blocks [1024,...) = W conversion
__global__ void k_convrouter(const float* __restrict__ x, const float* __restrict__ Wr,
                             const float* __restrict__ br, const float4* __restrict__ W4) {
    if (blockIdx.x >= TT / 8) {
        size_t i = (size_t)(blockIdx.x - TT / 8) * 256 + threadIdx.x;
        ((uint2*)g_Wf)[i] = cvt4_h(W4[i]);
        return;
    }
    int t = blockIdx.x * 8 + (threadIdx.x >> 5);
    int lid = threadIdx.x & 31;
    const float4* xr = (const float4*)(x + (size_t)t * DD);
    const float4* wr = (const float4*)Wr;
    uint2* xo = (uint2*)(g_xf + (size_t)t * DD);
    float acc[EE];
#pragma unroll
    for (int e = 0; e < EE; e++) acc[e] = 0.f;
    for (int i = lid; i < DD / 4; i += 32) {
        float4 xv = xr[i];
        xo[i] = cvt4_h(xv);
#pragma unroll
        for (int e = 0; e < EE; e++) {
            float4 w = wr[e * (DD / 4) + i];
            acc[e] += xv.x * w.x + xv.y * w.y + xv.z * w.z + xv.w * w.w;
        }
    }
#pragma unroll
    for (int e = 0; e < EE; e++)
#pragma unroll
        for (int o = 16; o; o >>= 1) acc[e] += __shfl_xor_sync(0xffffffffu, acc[e], o);
    if (lid == 0) {
        float mx = -1e30f; int idx = 0;
#pragma unroll
        for (int e = 0; e < EE; e++) {
            acc[e] += br[e];
            if (acc[e] > mx) { mx = acc[e]; idx = e; }
        }
        float s = 0.f;
#pragma unroll
        for (int e = 0; e < EE; e++) s += expf(acc[e] - mx);
        float tp = 1.f / s;
        g_expert[t] = idx; g_topp[t] = tp;
        atomicAdd(&g_cnt[idx], 1);
        atomicAdd(&g_tpsum[idx], tp);
    }
}

// fillmap: build row2tok via per-thread prefix over g_cnt; thread 0 of block 0 writes loss
__global__ void k_fillmap(float* __restrict__ out, int out_size) {
    int t = blockIdx.x * 256 + threadIdx.x;
    if (t < TT) {
        int e = g_expert[t];
        int base = 0;
#pragma unroll
        for (int i = 0; i < EE; i++)
            if (i < e) base += ((g_cnt[i] + MT - 1) / MT) * MT;
        int r = base + atomicAdd(&g_cursor[e], 1);
        g_row2tok[r] = t;
    }
    if (blockIdx.x == 0 && threadIdx.x == 0) {
        float loss = 0.f;
#pragma unroll
        for (int e = 0; e < EE; e++) {
            float frac = (float)g_cnt[e] / (float)TT;
            float prob = g_tpsum[e] / ((float)TT * (float)TT);
            loss += frac * prob;
        }
        loss *= 3e-06f * (float)EE;
        if (out_size == TT * DD + 1) out[(size_t)TT * DD] = loss;
    }
}

// ------ GEMM (HMMA fp16, 128x128 CTA, 4 warps, warp 64x64, occ 2, ks-pipelined) -------
__global__ void __launch_bounds__(128, 2)
k_gemm(const float* __restrict__ bias, float* __restrict__ out) {
    int mtile = blockIdx.y, ntile = blockIdx.x;

    // inline schedule: which expert owns this mtile?
    int e = -1, nt_total = 0;
#pragma unroll
    for (int i = 0; i < EE; i++) {
        int tiles = (g_cnt[i] + MT - 1) / MT;
        if (mtile >= nt_total && mtile < nt_total + tiles) e = i;
        nt_total += tiles;
    }
    if (e < 0) return;

    extern __shared__ char smem[];
    uint32_t tiles0 = smem_u32(smem);

    int tid = threadIdx.x, wid = tid >> 5, lane = tid & 31;
    int wm = wid >> 1, wn = wid & 1;          // 2 x 2 warp grid, warp tile 64x64

    const __half* Bsrc0 = g_Wf + ((size_t)e * DD + (size_t)ntile * NT) * DD;

    // loader: 8 threads per 128B row
    int lrow = tid >> 3, lp = tid & 7;
    const char* Bg = (const char*)Bsrc0 + lp * 16;

    // indirect A row pointers (gather through row2tok, zero-fill pads)
    const char* aptr[8];
    uint32_t asz[8];
#pragma unroll
    for (int p = 0; p < 8; p++) {
        int tok = g_row2tok[mtile * MT + lrow + p * 16];
        asz[p] = (tok >= 0) ? 16u : 0u;
        aptr[p] = (const char*)(g_xf + (size_t)(tok < 0 ? 0 : tok) * DD) + lp * 16;
    }

    auto load_chunk = [&](int c, int slot) {
        uint32_t abase = tiles0 + slot * STAGE_BYTES;
        uint32_t bbase = abase + A_BYTES;
        size_t coff = (size_t)c * (KC * 2);
#pragma unroll
        for (int p = 0; p < 8; p++) {
            int r = lrow + p * 16;
            uint32_t soff = (uint32_t)r * 128u + (uint32_t)((lp ^ (r & 7)) << 4);
            cp_async16z(abase + soff, aptr[p] + coff, asz[p]);
            cp_async16(bbase + soff, Bg + coff + (size_t)r * (DD * 2));
        }
        asm volatile("cp.async.commit_group;" ::: "memory");
    };

    // ldmatrix address components (constant over chunks)
    int khA = (lane >> 4) & 1;
    int khB = (lane >> 3) & 1;
    uint32_t aob[4]; int asw[4];
#pragma unroll
    for (int mf = 0; mf < 4; mf++) {
        int r = wm * 64 + mf * 16 + (lane & 7) + 8 * ((lane >> 3) & 1);
        aob[mf] = (uint32_t)r * 128u;
        asw[mf] = r & 7;
    }
    uint32_t bob[4]; int bsw[4];
#pragma unroll
    for (int p = 0; p < 4; p++) {
        int n = wn * 64 + p * 16 + (lane & 7) + 8 * ((lane >> 4) & 1);
        bob[p] = (uint32_t)n * 128u;
        bsw[p] = n & 7;
    }

    float acc[4][8][4];
#pragma unroll
    for (int i = 0; i < 4; i++)
#pragma unroll
        for (int j = 0; j < 8; j++)
#pragma unroll
            for (int q = 0; q < 4; q++) acc[i][j][q] = 0.f;

    // fragment double buffers
    uint32_t aF[2][4][4], bF[2][8][2];

    auto ld_frags = [&](uint32_t as, uint32_t bs, int ks, int buf) {
#pragma unroll
        for (int mf = 0; mf < 4; mf++)
            ldsm_x4(aF[buf][mf][0], aF[buf][mf][1], aF[buf][mf][2], aF[buf][mf][3],
                    as + aob[mf] + (uint32_t)(((ks * 2 + khA) ^ asw[mf]) << 4));
#pragma unroll
        for (int p = 0; p < 4; p++)
            ldsm_x4(bF[buf][2 * p][0], bF[buf][2 * p][1],
                    bF[buf][2 * p + 1][0], bF[buf][2 * p + 1][1],
                    bs + bob[p] + (uint32_t)(((ks * 2 + khB) ^ bsw[p]) << 4));
    };

    // prologue: fill 2 stages
    load_chunk(0, 0);
    load_chunk(1, 1);

    int slot = 0;
    for (int c = 0; c < CHUNKS; c++) {
        asm volatile("cp.async.wait_group 1;" ::: "memory");
        __syncthreads();

        uint32_t as = tiles0 + slot * STAGE_BYTES;
        uint32_t bs = as + A_BYTES;
        ld_frags(as, bs, 0, 0);                 // start MMA critical path first

        int nslot = slot + 2; if (nslot >= STAGES) nslot -= STAGES;
        if (c + 2 < CHUNKS) load_chunk(c + 2, nslot);
        else asm volatile("cp.async.commit_group;" ::: "memory");

#pragma unroll
        for (int ks = 0; ks < 4; ks++) {
            int cb = ks & 1;
            if (ks < 3) ld_frags(as, bs, ks + 1, cb ^ 1);
#pragma unroll
            for (int mf = 0; mf < 4; mf++)
#pragma unroll
                for (int nf = 0; nf < 8; nf++)
                    mma_f16(acc[mf][nf], aF[cb][mf], bF[cb][nf]);
        }
        if (++slot == STAGES) slot = 0;
    }

    // epilogue: (acc + bias) * topp, scatter rows to tokens
    int g = lane >> 2, tq = lane & 3;
    const float* brow = bias + (size_t)e * DD + (size_t)ntile * NT;
#pragma unroll
    for (int mf = 0; mf < 4; mf++) {
#pragma unroll
        for (int half = 0; half < 2; half++) {
            int m = mtile * MT + wm * 64 + mf * 16 + g + half * 8;
            int tok = g_row2tok[m];
            if (tok < 0) continue;
            float tp = g_topp[tok];
            float* orow = out + (size_t)tok * DD + (size_t)ntile * NT;
#pragma unroll
            for (int nf = 0; nf < 8; nf++) {
                int n = wn * 64 + nf * 8 + 2 * tq;
                float2 o;
                o.x = (acc[mf][nf][half * 2 + 0] + brow[n]) * tp;
                o.y = (acc[mf][nf][half * 2 + 1] + brow[n + 1]) * tp;
                *(float2*)(orow + n) = o;
            }
        }
    }
}

// ---------------- launcher ----------------
extern "C" void kernel_launch(void* const* d_in, const int* in_sizes, int n_in,
                              void* d_out, int out_size) {
    const float* x  = (const float*)d_in[0];
    const float* Wr = (const float*)d_in[1];
    const float* br = (const float*)d_in[2];
    const float* W  = (const float*)d_in[3];
    const float* b  = (const float*)d_in[4];
    float* out = (float*)d_out;

    cudaFuncSetAttribute(k_gemm, cudaFuncAttributeMaxDynamicSharedMemorySize, SMEM_NEED);

    k_reset<<<(NROWS + 255) / 256, 256>>>();
    k_convrouter<<<TT / 8 + (int)((size_t)EE * DD * DD / 4 / 256), 256>>>(
        x, Wr, br, (const float4*)W);
    k_fillmap<<<TT / 256, 256>>>(out, out_size);
    k_gemm<<<dim3(DD / NT, MAX_MTILES), 128, SMEM_NEED>>>(b, out);
}